// round 15
// baseline (speedup 1.0000x reference)
#include <cuda_runtime.h>
#include <cuda_bf16.h>

#define NEL     20000      // B*NE total electrons
#define T_TICKS 512
#define NXY     48
#define TT      16         // ticks per tile
#define NTILE   32         // 512/16
#define SXC     6          // sensor-x rows per strip
#define NSTRIP  8          // 48/6
#define WCUT    8          // temporal truncation half-window
#define NB      128        // z buckets (width 4 ticks)
#define CHUNK   64         // electrons per SMEM pass
#define BLK_D   160        // 5 warps; 144 active compute threads
#define ACT_D   144        // 6 sx rows x 24 sensor-pair columns
#define NSB     (NSTRIP*NB)
#define MAXENT  (NEL*8)
#define RECF4   2             // 32B compact record: gx[6], z, pad
#define RECB    32
#define GYB     192           // one c*gy row
#define NSPLIT  4
#define VOL     (NXY*NXY*T_TICKS)

// ---- scratch (__device__ globals; no allocation allowed) ----
__device__ float  g_gx [NEL * 48];   // raw gaussian in x, per electron (index order)
__device__ float  g_cgy[NEL * 48];   // c * gaussian in y (index order)
__device__ float  g_z  [NEL];
__device__ float  g_ex [NEL];
__device__ int    g_rank[NSTRIP * NEL];  // rank within (strip,bucket) cell
__device__ int    g_scount[NSB];
__device__ int    g_soff  [NSB + 1];
__device__ float4 g_ent [MAXENT * RECF4]; // compact records
__device__ int    g_eidx[MAXENT];         // entry -> electron index

// ---- packed f32x2 helpers ----
__device__ __forceinline__ unsigned long long pack2(float v) {
    unsigned long long r;
    unsigned u = __float_as_uint(v);
    asm("mov.b64 %0, {%1, %1};" : "=l"(r) : "r"(u));
    return r;
}
__device__ __forceinline__ void fma2(unsigned long long& acc,
                                     unsigned long long a, unsigned long long b) {
    asm("fma.rn.f32x2 %0, %1, %2, %0;" : "+l"(acc) : "l"(a), "l"(b));
}
__device__ __forceinline__ void unpack2(unsigned long long p, float& lo, float& hi) {
    unsigned a, b;
    asm("mov.b64 {%0, %1}, %2;" : "=r"(a), "=r"(b) : "l"(p));
    lo = __uint_as_float(a); hi = __uint_as_float(b);
}
__device__ __forceinline__ void red_add_v4(float* gptr, float a, float b,
                                           float c, float d) {
    asm volatile("red.global.add.v4.f32 [%0], {%1, %2, %3, %4};"
                 :: "l"(gptr), "f"(a), "f"(b), "f"(c), "f"(d) : "memory");
}

// ---- mbarrier / bulk-copy helpers ----
__device__ __forceinline__ unsigned smem_u32(const void* p) {
    return (unsigned)__cvta_generic_to_shared(p);
}
__device__ __forceinline__ void mbar_init(unsigned mbar, unsigned cnt) {
    asm volatile("mbarrier.init.shared.b64 [%0], %1;" :: "r"(mbar), "r"(cnt) : "memory");
}
__device__ __forceinline__ void mbar_expect_tx(unsigned mbar, unsigned bytes) {
    asm volatile("mbarrier.arrive.expect_tx.shared.b64 _, [%0], %1;"
                 :: "r"(mbar), "r"(bytes) : "memory");
}
__device__ __forceinline__ void bulk_g2s(unsigned dst, const void* src,
                                         unsigned bytes, unsigned mbar) {
    asm volatile("cp.async.bulk.shared::cta.global.mbarrier::complete_tx::bytes "
                 "[%0], [%1], %2, [%3];"
                 :: "r"(dst), "l"(src), "r"(bytes), "r"(mbar) : "memory");
}
__device__ __forceinline__ void mbar_wait(unsigned mbar, unsigned parity) {
    asm volatile(
        "{\n\t"
        ".reg .pred P1;\n\t"
        "WAIT_LOOP_%=:\n\t"
        "mbarrier.try_wait.parity.acquire.cta.shared::cta.b64 P1, [%0], %1, 0x989680;\n\t"
        "@P1 bra.uni WAIT_DONE_%=;\n\t"
        "bra.uni WAIT_LOOP_%=;\n\t"
        "WAIT_DONE_%=:\n\t"
        "}"
        :: "r"(mbar), "r"(parity) : "memory");
}

// ------------------------------------------------------------------
// exclusive scan of the 1024 (strip,bucket) cells
__global__ void k_scan() {
    __shared__ int sd[NSB];
    int tid = threadIdx.x;
    int v = g_scount[tid];
    sd[tid] = v; __syncthreads();
    for (int d = 1; d < NSB; d <<= 1) {
        int add = (tid >= d) ? sd[tid - d] : 0;
        __syncthreads();
        sd[tid] += add;
        __syncthreads();
    }
    g_soff[tid] = sd[tid] - v;
    if (tid == NSB - 1) g_soff[NSB] = sd[tid];
}

// ------------------------------------------------------------------
// Per-electron precompute. 16 threads per 8 electrons; o owns h2 dims
// [8o,8o+8) packed f32x2. r==0 lane records ranks for the scatter.
__global__ __launch_bounds__(128) void k_pre(
                      const float* __restrict__ si, const float* __restrict__ zp,
                      const float* __restrict__ mk,
                      const float* __restrict__ W1, const float* __restrict__ b1,
                      const float* __restrict__ W2, const float* __restrict__ b2,
                      const float* __restrict__ W3, const float* __restrict__ b3,
                      const float* __restrict__ el, const float* __restrict__ sloc)
{
    __shared__ float  W1s[128], b1s[64];
    __shared__ float4 W2s4[64 * 32];
    __shared__ unsigned long long b2u[64];
    __shared__ float  W3s[128];
    __shared__ float  axs[48], ays[48];
    __shared__ float  sxlo[NSTRIP], sxhi[NSTRIP];
    int tid = threadIdx.x;
    if (tid < 128) W1s[tid] = W1[tid];
    if (tid < 64)  b1s[tid] = b1[tid];
    {
        const float4* w2 = (const float4*)W2;
        for (int i = tid; i < 64 * 32; i += blockDim.x) W2s4[i] = w2[i];
    }
    if (tid < 64)  b2u[tid] = ((const unsigned long long*)b2)[tid];
    if (tid < 128) W3s[tid] = W3[tid];
    if (tid < 48)  { axs[tid] = sloc[tid * 96]; ays[tid] = sloc[tid * 2 + 1]; }
    if (tid < NSTRIP) {
        sxlo[tid] = sloc[(tid * SXC) * 96];
        sxhi[tid] = sloc[(tid * SXC + SXC - 1) * 96];
    }
    __syncthreads();

    int o    = tid & 15;
    int grp  = tid >> 4;                      // 8 groups per CTA
    int gbase = (blockIdx.x * 8 + grp) * 8;   // 8 electrons per group
    if (gbase >= NEL) return;

    float xs[8], ys[8];
#pragma unroll
    for (int i = 0; i < 8; i++) { xs[i] = si[2 * (gbase + i)]; ys[i] = si[2 * (gbase + i) + 1]; }

    unsigned long long h2p[8][4];
#pragma unroll
    for (int e = 0; e < 8; e++)
#pragma unroll
        for (int dp = 0; dp < 4; dp++) h2p[e][dp] = b2u[o * 4 + dp];

    const ulonglong2* W2u2 = (const ulonglong2*)W2s4;
    for (int k4 = 0; k4 < 16; k4++) {
        float4 wa  = ((const float4*)W1s)[k4];
        float4 wb  = ((const float4*)(W1s + 64))[k4];
        float4 bb4 = ((const float4*)b1s)[k4];
#pragma unroll
        for (int kk = 0; kk < 4; kk++) {
            int k = 4 * k4 + kk;
            float w1a = (&wa.x)[kk], w1b = (&wb.x)[kk], bb = (&bb4.x)[kk];
            unsigned long long hp[8];
#pragma unroll
            for (int e = 0; e < 8; e++) {
                float h1 = fmaxf(fmaf(xs[e], w1a, fmaf(ys[e], w1b, bb)), 0.0f);
                hp[e] = pack2(h1);
            }
#pragma unroll
            for (int q = 0; q < 2; q++) {
                ulonglong2 w = W2u2[k * 32 + o * 2 + q];
#pragma unroll
                for (int e = 0; e < 8; e++) {
                    fma2(h2p[e][2 * q],     hp[e], w.x);
                    fma2(h2p[e][2 * q + 1], hp[e], w.y);
                }
            }
        }
    }

    float rp[8] = {0.f, 0.f, 0.f, 0.f, 0.f, 0.f, 0.f, 0.f};
#pragma unroll
    for (int dp = 0; dp < 4; dp++) {
        float w3lo = W3s[o * 8 + 2 * dp];
        float w3hi = W3s[o * 8 + 2 * dp + 1];
#pragma unroll
        for (int e = 0; e < 8; e++) {
            float lo, hi;
            unpack2(h2p[e][dp], lo, hi);
            rp[e] = fmaf(fmaxf(lo, 0.f), w3lo, rp[e]);
            rp[e] = fmaf(fmaxf(hi, 0.f), w3hi, rp[e]);
        }
    }
#pragma unroll
    for (int d = 1; d < 16; d <<= 1)
#pragma unroll
        for (int e = 0; e < 8; e++)
            rp[e] += __shfl_xor_sync(0xffffffffu, rp[e], d);

    float es = el[0];
    float inv = -0.5f / (es * es);
    float cnorm = (100.0f / (es * 2.5066f)) * 0.17841241161f;
    float thr = 4.57f * es;
    float b3v = b3[0];

    // epilogue twice: 4 lanes per electron, electrons myE and myE+4
#pragma unroll
    for (int half = 0; half < 2; half++) {
        int myE = (o >> 2) + 4 * half;
        int r   = o & 3;
        int ei  = gbase + myE;
        float resp = rp[myE] + b3v;
        float c = resp * mk[ei] * cnorm;
        float z = zp[ei];
        float x = xs[myE], y = ys[myE];

        if (r < 2) {
            float4* pgx = (float4*)(g_gx + (size_t)ei * 48);
#pragma unroll
            for (int q = 0; q < 6; q++) {
                int qq = r * 6 + q;
                float d0 = x - axs[4 * qq + 0], d1 = x - axs[4 * qq + 1];
                float d2 = x - axs[4 * qq + 2], d3 = x - axs[4 * qq + 3];
                pgx[qq] = make_float4(__expf(d0 * d0 * inv), __expf(d1 * d1 * inv),
                                      __expf(d2 * d2 * inv), __expf(d3 * d3 * inv));
            }
            if (r == 0) {
                g_z[ei]  = z;
                g_ex[ei] = x;
                int b = min(max((int)z >> 2, 0), NB - 1);
#pragma unroll
                for (int s = 0; s < NSTRIP; s++) {
                    float dd = fmaxf(fmaxf(sxlo[s] - x, x - sxhi[s]), 0.0f);
                    if (dd < thr) {
                        int rank = atomicAdd(&g_scount[s * NB + b], 1);
                        g_rank[s * NEL + ei] = rank;
                    }
                }
            }
        } else {
            float4* pgy = (float4*)(g_cgy + (size_t)ei * 48);
#pragma unroll
            for (int q = 0; q < 6; q++) {
                int qq = (r - 2) * 6 + q;
                float d0 = y - ays[4 * qq + 0], d1 = y - ays[4 * qq + 1];
                float d2 = y - ays[4 * qq + 2], d3 = y - ays[4 * qq + 3];
                pgy[qq] = make_float4(c * __expf(d0 * d0 * inv), c * __expf(d1 * d1 * inv),
                                      c * __expf(d2 * d2 * inv), c * __expf(d3 * d3 * inv));
            }
        }
    }
}

// ------------------------------------------------------------------
// Compact scatter: lane r handles (electron, strip r) independently.
__global__ __launch_bounds__(256) void k_scatter(const float* __restrict__ el,
                                                 const float* __restrict__ sloc) {
    __shared__ float sxlo[NSTRIP], sxhi[NSTRIP];
    if (threadIdx.x < NSTRIP) {
        sxlo[threadIdx.x] = sloc[(threadIdx.x * SXC) * 96];
        sxhi[threadIdx.x] = sloc[(threadIdx.x * SXC + SXC - 1) * 96];
    }
    __syncthreads();
    int tid = threadIdx.x;
    int r   = tid & 7;
    int ei  = blockIdx.x * 32 + (tid >> 3);
    if (ei >= NEL) return;

    float x = g_ex[ei];
    float dd = fmaxf(fmaxf(sxlo[r] - x, x - sxhi[r]), 0.0f);
    if (dd >= 4.57f * el[0]) return;

    float z = g_z[ei];
    int b = min(max((int)z >> 2, 0), NB - 1);
    int pos = g_soff[r * NB + b] + g_rank[r * NEL + ei];

    const float2* gx2 = (const float2*)(g_gx + (size_t)ei * 48);
    float2 a = gx2[3 * r], c = gx2[3 * r + 1], d = gx2[3 * r + 2];
    float4* ent = &g_ent[(size_t)pos * RECF4];
    ent[0] = make_float4(a.x, a.y, c.x, c.y);
    ent[1] = make_float4(d.x, d.y, z, 0.0f);
    g_eidx[pos] = ei;
}

// ------------------------------------------------------------------
// Main accumulation: CTA = (t-tile of 16 ticks, strip, split4).
// Staging per chunk: 1 bulk copy of records + 64 per-row bulk gathers
// of c*gy, double-buffered. 144 active threads x 2 sensors, 16 packed
// FMAs per entry. Result reduced straight into out via red.global.v4.
__global__ __launch_bounds__(BLK_D) void k_main(float* __restrict__ out)
{
    __shared__ float4     s_rec[2][CHUNK * RECF4];   // 4 KB
    __shared__ float      s_gy [2][CHUNK * 48];      // 24 KB
    __shared__ ulonglong2 s_ev2[CHUNK * 4];          // 8 KB (16 ticks/entry)
    __shared__ unsigned long long s_mb[2];

    int tid = threadIdx.x;
    int t0  = blockIdx.x * TT;
    int s   = blockIdx.y;
    int sxl = tid / 24;          // 0..5 for active threads
    int q   = tid - sxl * 24;    // sensor-pair column 0..23

    unsigned mb[2]   = { smem_u32(&s_mb[0]), smem_u32(&s_mb[1]) };
    unsigned rdst[2] = { smem_u32(&s_rec[0][0]), smem_u32(&s_rec[1][0]) };
    unsigned gdst[2] = { smem_u32(&s_gy[0][0]),  smem_u32(&s_gy[1][0]) };
    if (tid == 0) { mbar_init(mb[0], 1); mbar_init(mb[1], 1); }
    __syncthreads();

    int blo = max(t0 - WCUT, 0) >> 2;
    int bhi = min(t0 + TT - 1 + WCUT, T_TICKS - 1) >> 2;
    int rb = g_soff[s * NB + blo], re = g_soff[s * NB + bhi + 1];
    int len = re - rb;
    int part = (len + NSPLIT - 1) / NSPLIT;
    int cb = rb + blockIdx.z * part;
    int ce = min(cb + part, re);
    int nch = (ce > cb) ? (ce - cb + CHUNK - 1) / CHUNK : 0;

    unsigned long long aa[8], ab[8];
#pragma unroll
    for (int j = 0; j < 8; j++) { aa[j] = 0ull; ab[j] = 0ull; }

    int ph0 = 0, ph1 = 0;

    // prefetch chunk 0
    if (nch > 0) {
        int cnt0 = min(CHUNK, ce - cb);
        if (tid == 0) mbar_expect_tx(mb[0], (unsigned)cnt0 * (RECB + GYB));
        __syncthreads();               // expect_tx ordered before completions
        if (tid == 0)
            bulk_g2s(rdst[0], (const char*)&g_ent[(size_t)cb * RECF4],
                     (unsigned)cnt0 * RECB, mb[0]);
        if (tid < cnt0) {
            int idx = g_eidx[cb + tid];
            bulk_g2s(gdst[0] + tid * GYB, g_cgy + (size_t)idx * 48, GYB, mb[0]);
        }
    }

    for (int ch = 0; ch < nch; ch++) {
        int c0  = cb + ch * CHUNK;
        int cnt = min(CHUNK, ce - c0);
        int buf = ch & 1;
        int nb_ = buf ^ 1;

        __syncthreads();                    // compute(ch-1) done: buf^1 + s_ev2 free
        int c1 = c0 + CHUNK;
        int cnt1 = (ch + 1 < nch) ? min(CHUNK, ce - c1) : 0;
        if (cnt1 > 0 && tid == 0)
            mbar_expect_tx(mb[nb_], (unsigned)cnt1 * (RECB + GYB));
        __syncthreads();                    // order expect before completions
        if (cnt1 > 0) {
            if (tid == 0)
                bulk_g2s(rdst[nb_], (const char*)&g_ent[(size_t)c1 * RECF4],
                         (unsigned)cnt1 * RECB, mb[nb_]);
            if (tid < cnt1) {
                int idx = g_eidx[c1 + tid];
                bulk_g2s(gdst[nb_] + tid * GYB, g_cgy + (size_t)idx * 48, GYB, mb[nb_]);
            }
        }
        // wait for chunk ch
        if (buf == 0) { mbar_wait(mb[0], ph0); ph0 ^= 1; }
        else          { mbar_wait(mb[1], ph1); ph1 ^= 1; }

        // ev via recurrence over 16 ticks:
        // exp(-0.1(d+1)^2) = exp(-0.1 d^2) * exp(-0.2 d - 0.1)
        if (tid < cnt) {
            float z  = ((const float*)&s_rec[buf][tid * RECF4])[6];
            float d  = (float)t0 - z;
            float e  = __expf(-0.1f * d * d);
            float rr = __expf(fmaf(-0.2f, d, -0.1f));
            const float rs = 0.81873075308f;   // exp(-0.2)
            float ev[16];
            ev[0] = e;
#pragma unroll
            for (int k = 1; k < 16; k++) {
                e *= rr; rr *= rs; ev[k] = e;
            }
            float4* dv = (float4*)&s_ev2[tid * 4];
#pragma unroll
            for (int j = 0; j < 4; j++)
                dv[j] = make_float4(ev[4 * j], ev[4 * j + 1], ev[4 * j + 2], ev[4 * j + 3]);
        }
        __syncthreads();

        if (tid < ACT_D) {
            const float* gyb = s_gy[buf];
#pragma unroll 2
            for (int e = 0; e < cnt; e++) {
                float gxv = ((const float*)&s_rec[buf][e * RECF4])[sxl];
                float2 gy2 = *(const float2*)(gyb + e * 48 + 2 * q);
                unsigned long long va2 = pack2(gxv * gy2.x);
                unsigned long long vb2 = pack2(gxv * gy2.y);
                const ulonglong2* wp = &s_ev2[e * 4];
#pragma unroll
                for (int j = 0; j < 4; j++) {
                    ulonglong2 w = wp[j];
                    fma2(aa[2 * j],     va2, w.x); fma2(ab[2 * j],     vb2, w.x);
                    fma2(aa[2 * j + 1], va2, w.y); fma2(ab[2 * j + 1], vb2, w.y);
                }
            }
        }
    }

    if (tid < ACT_D) {
        float fa[16], fb[16];
#pragma unroll
        for (int j = 0; j < 8; j++) {
            unpack2(aa[j], fa[2 * j], fa[2 * j + 1]);
            unpack2(ab[j], fb[2 * j], fb[2 * j + 1]);
        }
        int sx = s * SXC + sxl;
        int sy = 2 * q;
        float* oa = out + ((size_t)(sx * NXY + sy)) * T_TICKS + t0;
        float* ob = out + ((size_t)(sx * NXY + sy + 1)) * T_TICKS + t0;
#pragma unroll
        for (int j = 0; j < 4; j++) {
            red_add_v4(oa + 4 * j, fa[4 * j], fa[4 * j + 1], fa[4 * j + 2], fa[4 * j + 3]);
            red_add_v4(ob + 4 * j, fb[4 * j], fb[4 * j + 1], fb[4 * j + 2], fb[4 * j + 3]);
        }
    }
}

// ------------------------------------------------------------------
extern "C" void kernel_launch(void* const* d_in, const int* in_sizes, int n_in,
                              void* d_out, int out_size)
{
    const float* si = (const float*)d_in[0];
    const float* zp = (const float*)d_in[1];
    const float* mk = (const float*)d_in[2];
    const float* W1 = (const float*)d_in[3];
    const float* b1 = (const float*)d_in[4];
    const float* W2 = (const float*)d_in[5];
    const float* b2 = (const float*)d_in[6];
    const float* W3 = (const float*)d_in[7];
    const float* b3 = (const float*)d_in[8];
    const float* el = (const float*)d_in[9];
    const float* sl = (const float*)d_in[10];
    float* out = (float*)d_out;                // (48,48,512)

    void* scnt_ptr = nullptr;
    cudaGetSymbolAddress(&scnt_ptr, g_scount);
    cudaMemsetAsync(scnt_ptr, 0, NSB * sizeof(int), 0);
    cudaMemsetAsync(d_out, 0, (size_t)out_size * sizeof(float), 0);

    k_pre    <<<(NEL + 63) / 64, 128>>>(si, zp, mk, W1, b1, W2, b2, W3, b3, el, sl);
    k_scan   <<<1, NSB>>>();
    k_scatter<<<(NEL + 31) / 32, 256>>>(el, sl);
    k_main   <<<dim3(NTILE, NSTRIP, NSPLIT), BLK_D>>>(out);
}

// round 16
// speedup vs baseline: 1.2930x; 1.2930x over previous
#include <cuda_runtime.h>
#include <cuda_bf16.h>

#define NEL     20000      // B*NE total electrons
#define T_TICKS 512
#define NXY     48
#define TT      8          // ticks per tile
#define NTILE   64         // 512/8
#define SXC     6          // sensor-x rows per strip
#define NSTRIP  8          // 48/6
#define WCUT    8          // temporal truncation half-window
#define NB      128        // z buckets (width 4 ticks)
#define CHUNK   64         // electrons per SMEM pass
#define BLK_D   160        // 5 warps; 144 active compute threads
#define ACT_D   144        // 6 sx rows x 24 sensor-pair columns
#define NSB     (NSTRIP*NB)
#define MAXENT  (NEL*8)
#define RECF4   2             // 32B compact record: gx[6], z, pad
#define RECB    32
#define GYB     192           // one c*gy row
#define NSPLIT  4

// ---- scratch (__device__ globals; no allocation allowed) ----
__device__ float  g_gx [NEL * 48];   // raw gaussian in x, per electron (index order)
__device__ float  g_cgy[NEL * 48];   // c * gaussian in y (index order)
__device__ float  g_z  [NEL];
__device__ float  g_ex [NEL];
__device__ int    g_rank[NSTRIP * NEL];  // rank within (strip,bucket) cell
__device__ int    g_scount[NSB];
__device__ int    g_soff  [NSB + 1];
__device__ float4 g_ent [MAXENT * RECF4]; // compact records
__device__ int    g_eidx[MAXENT];         // entry -> electron index

// ---- packed f32x2 helpers ----
__device__ __forceinline__ unsigned long long pack2(float v) {
    unsigned long long r;
    unsigned u = __float_as_uint(v);
    asm("mov.b64 %0, {%1, %1};" : "=l"(r) : "r"(u));
    return r;
}
__device__ __forceinline__ void fma2(unsigned long long& acc,
                                     unsigned long long a, unsigned long long b) {
    asm("fma.rn.f32x2 %0, %1, %2, %0;" : "+l"(acc) : "l"(a), "l"(b));
}
__device__ __forceinline__ void unpack2(unsigned long long p, float& lo, float& hi) {
    unsigned a, b;
    asm("mov.b64 {%0, %1}, %2;" : "=r"(a), "=r"(b) : "l"(p));
    lo = __uint_as_float(a); hi = __uint_as_float(b);
}
__device__ __forceinline__ void red_add_v4(float* gptr, float a, float b,
                                           float c, float d) {
    asm volatile("red.global.add.v4.f32 [%0], {%1, %2, %3, %4};"
                 :: "l"(gptr), "f"(a), "f"(b), "f"(c), "f"(d) : "memory");
}

// ---- mbarrier / bulk-copy helpers ----
__device__ __forceinline__ unsigned smem_u32(const void* p) {
    return (unsigned)__cvta_generic_to_shared(p);
}
__device__ __forceinline__ void mbar_init(unsigned mbar, unsigned cnt) {
    asm volatile("mbarrier.init.shared.b64 [%0], %1;" :: "r"(mbar), "r"(cnt) : "memory");
}
__device__ __forceinline__ void mbar_expect_tx(unsigned mbar, unsigned bytes) {
    asm volatile("mbarrier.arrive.expect_tx.shared.b64 _, [%0], %1;"
                 :: "r"(mbar), "r"(bytes) : "memory");
}
__device__ __forceinline__ void bulk_g2s(unsigned dst, const void* src,
                                         unsigned bytes, unsigned mbar) {
    asm volatile("cp.async.bulk.shared::cta.global.mbarrier::complete_tx::bytes "
                 "[%0], [%1], %2, [%3];"
                 :: "r"(dst), "l"(src), "r"(bytes), "r"(mbar) : "memory");
}
__device__ __forceinline__ void mbar_wait(unsigned mbar, unsigned parity) {
    asm volatile(
        "{\n\t"
        ".reg .pred P1;\n\t"
        "WAIT_LOOP_%=:\n\t"
        "mbarrier.try_wait.parity.acquire.cta.shared::cta.b64 P1, [%0], %1, 0x989680;\n\t"
        "@P1 bra.uni WAIT_DONE_%=;\n\t"
        "bra.uni WAIT_LOOP_%=;\n\t"
        "WAIT_DONE_%=:\n\t"
        "}"
        :: "r"(mbar), "r"(parity) : "memory");
}

// ------------------------------------------------------------------
// exclusive scan of the 1024 (strip,bucket) cells
__global__ void k_scan() {
    __shared__ int sd[NSB];
    int tid = threadIdx.x;
    int v = g_scount[tid];
    sd[tid] = v; __syncthreads();
    for (int d = 1; d < NSB; d <<= 1) {
        int add = (tid >= d) ? sd[tid - d] : 0;
        __syncthreads();
        sd[tid] += add;
        __syncthreads();
    }
    g_soff[tid] = sd[tid] - v;
    if (tid == NSB - 1) g_soff[NSB] = sd[tid];
}

// ------------------------------------------------------------------
// Per-electron precompute. 16 threads per 8 electrons; o owns h2 dims
// [8o,8o+8) packed f32x2. r==0 lane records ranks for the scatter.
__global__ __launch_bounds__(128) void k_pre(
                      const float* __restrict__ si, const float* __restrict__ zp,
                      const float* __restrict__ mk,
                      const float* __restrict__ W1, const float* __restrict__ b1,
                      const float* __restrict__ W2, const float* __restrict__ b2,
                      const float* __restrict__ W3, const float* __restrict__ b3,
                      const float* __restrict__ el, const float* __restrict__ sloc)
{
    __shared__ float  W1s[128], b1s[64];
    __shared__ float4 W2s4[64 * 32];
    __shared__ unsigned long long b2u[64];
    __shared__ float  W3s[128];
    __shared__ float  axs[48], ays[48];
    __shared__ float  sxlo[NSTRIP], sxhi[NSTRIP];
    int tid = threadIdx.x;
    if (tid < 128) W1s[tid] = W1[tid];
    if (tid < 64)  b1s[tid] = b1[tid];
    {
        const float4* w2 = (const float4*)W2;
        for (int i = tid; i < 64 * 32; i += blockDim.x) W2s4[i] = w2[i];
    }
    if (tid < 64)  b2u[tid] = ((const unsigned long long*)b2)[tid];
    if (tid < 128) W3s[tid] = W3[tid];
    if (tid < 48)  { axs[tid] = sloc[tid * 96]; ays[tid] = sloc[tid * 2 + 1]; }
    if (tid < NSTRIP) {
        sxlo[tid] = sloc[(tid * SXC) * 96];
        sxhi[tid] = sloc[(tid * SXC + SXC - 1) * 96];
    }
    __syncthreads();

    int o    = tid & 15;
    int grp  = tid >> 4;                      // 8 groups per CTA
    int gbase = (blockIdx.x * 8 + grp) * 8;   // 8 electrons per group
    if (gbase >= NEL) return;

    float xs[8], ys[8];
#pragma unroll
    for (int i = 0; i < 8; i++) { xs[i] = si[2 * (gbase + i)]; ys[i] = si[2 * (gbase + i) + 1]; }

    unsigned long long h2p[8][4];
#pragma unroll
    for (int e = 0; e < 8; e++)
#pragma unroll
        for (int dp = 0; dp < 4; dp++) h2p[e][dp] = b2u[o * 4 + dp];

    const ulonglong2* W2u2 = (const ulonglong2*)W2s4;
    for (int k4 = 0; k4 < 16; k4++) {
        float4 wa  = ((const float4*)W1s)[k4];
        float4 wb  = ((const float4*)(W1s + 64))[k4];
        float4 bb4 = ((const float4*)b1s)[k4];
#pragma unroll
        for (int kk = 0; kk < 4; kk++) {
            int k = 4 * k4 + kk;
            float w1a = (&wa.x)[kk], w1b = (&wb.x)[kk], bb = (&bb4.x)[kk];
            unsigned long long hp[8];
#pragma unroll
            for (int e = 0; e < 8; e++) {
                float h1 = fmaxf(fmaf(xs[e], w1a, fmaf(ys[e], w1b, bb)), 0.0f);
                hp[e] = pack2(h1);
            }
#pragma unroll
            for (int q = 0; q < 2; q++) {
                ulonglong2 w = W2u2[k * 32 + o * 2 + q];
#pragma unroll
                for (int e = 0; e < 8; e++) {
                    fma2(h2p[e][2 * q],     hp[e], w.x);
                    fma2(h2p[e][2 * q + 1], hp[e], w.y);
                }
            }
        }
    }

    float rp[8] = {0.f, 0.f, 0.f, 0.f, 0.f, 0.f, 0.f, 0.f};
#pragma unroll
    for (int dp = 0; dp < 4; dp++) {
        float w3lo = W3s[o * 8 + 2 * dp];
        float w3hi = W3s[o * 8 + 2 * dp + 1];
#pragma unroll
        for (int e = 0; e < 8; e++) {
            float lo, hi;
            unpack2(h2p[e][dp], lo, hi);
            rp[e] = fmaf(fmaxf(lo, 0.f), w3lo, rp[e]);
            rp[e] = fmaf(fmaxf(hi, 0.f), w3hi, rp[e]);
        }
    }
#pragma unroll
    for (int d = 1; d < 16; d <<= 1)
#pragma unroll
        for (int e = 0; e < 8; e++)
            rp[e] += __shfl_xor_sync(0xffffffffu, rp[e], d);

    float es = el[0];
    float inv = -0.5f / (es * es);
    float cnorm = (100.0f / (es * 2.5066f)) * 0.17841241161f;
    float thr = 4.57f * es;
    float b3v = b3[0];

    // epilogue twice: 4 lanes per electron, electrons myE and myE+4
#pragma unroll
    for (int half = 0; half < 2; half++) {
        int myE = (o >> 2) + 4 * half;
        int r   = o & 3;
        int ei  = gbase + myE;
        float resp = rp[myE] + b3v;
        float c = resp * mk[ei] * cnorm;
        float z = zp[ei];
        float x = xs[myE], y = ys[myE];

        if (r < 2) {
            float4* pgx = (float4*)(g_gx + (size_t)ei * 48);
#pragma unroll
            for (int q = 0; q < 6; q++) {
                int qq = r * 6 + q;
                float d0 = x - axs[4 * qq + 0], d1 = x - axs[4 * qq + 1];
                float d2 = x - axs[4 * qq + 2], d3 = x - axs[4 * qq + 3];
                pgx[qq] = make_float4(__expf(d0 * d0 * inv), __expf(d1 * d1 * inv),
                                      __expf(d2 * d2 * inv), __expf(d3 * d3 * inv));
            }
            if (r == 0) {
                g_z[ei]  = z;
                g_ex[ei] = x;
                int b = min(max((int)z >> 2, 0), NB - 1);
#pragma unroll
                for (int s = 0; s < NSTRIP; s++) {
                    float dd = fmaxf(fmaxf(sxlo[s] - x, x - sxhi[s]), 0.0f);
                    if (dd < thr) {
                        int rank = atomicAdd(&g_scount[s * NB + b], 1);
                        g_rank[s * NEL + ei] = rank;
                    }
                }
            }
        } else {
            float4* pgy = (float4*)(g_cgy + (size_t)ei * 48);
#pragma unroll
            for (int q = 0; q < 6; q++) {
                int qq = (r - 2) * 6 + q;
                float d0 = y - ays[4 * qq + 0], d1 = y - ays[4 * qq + 1];
                float d2 = y - ays[4 * qq + 2], d3 = y - ays[4 * qq + 3];
                pgy[qq] = make_float4(c * __expf(d0 * d0 * inv), c * __expf(d1 * d1 * inv),
                                      c * __expf(d2 * d2 * inv), c * __expf(d3 * d3 * inv));
            }
        }
    }
}

// ------------------------------------------------------------------
// Compact scatter: lane r handles (electron, strip r) independently.
__global__ __launch_bounds__(256) void k_scatter(const float* __restrict__ el,
                                                 const float* __restrict__ sloc) {
    __shared__ float sxlo[NSTRIP], sxhi[NSTRIP];
    if (threadIdx.x < NSTRIP) {
        sxlo[threadIdx.x] = sloc[(threadIdx.x * SXC) * 96];
        sxhi[threadIdx.x] = sloc[(threadIdx.x * SXC + SXC - 1) * 96];
    }
    __syncthreads();
    int tid = threadIdx.x;
    int r   = tid & 7;
    int ei  = blockIdx.x * 32 + (tid >> 3);
    if (ei >= NEL) return;

    float x = g_ex[ei];
    float dd = fmaxf(fmaxf(sxlo[r] - x, x - sxhi[r]), 0.0f);
    if (dd >= 4.57f * el[0]) return;

    float z = g_z[ei];
    int b = min(max((int)z >> 2, 0), NB - 1);
    int pos = g_soff[r * NB + b] + g_rank[r * NEL + ei];

    const float2* gx2 = (const float2*)(g_gx + (size_t)ei * 48);
    float2 a = gx2[3 * r], c = gx2[3 * r + 1], d = gx2[3 * r + 2];
    float4* ent = &g_ent[(size_t)pos * RECF4];
    ent[0] = make_float4(a.x, a.y, c.x, c.y);
    ent[1] = make_float4(d.x, d.y, z, 0.0f);
    g_eidx[pos] = ei;
}

// ------------------------------------------------------------------
// Main accumulation: CTA = (t-tile of 8 ticks, strip, split4).
// Staging per chunk: 1 bulk copy of 32B records + 64 per-row bulk
// gathers of c*gy (indices from g_eidx), double-buffered. 144 active
// threads x 2 sensors, packed-f32x2 FMAs, epilogue reduced straight
// into out via red.global.add.v4.
__global__ __launch_bounds__(BLK_D) void k_main(float* __restrict__ out)
{
    __shared__ float4     s_rec[2][CHUNK * RECF4];   // 4 KB
    __shared__ float      s_gy [2][CHUNK * 48];      // 24 KB
    __shared__ ulonglong2 s_ev2[CHUNK * 2];          // 4 KB
    __shared__ unsigned long long s_mb[2];

    int tid = threadIdx.x;
    int t0  = blockIdx.x * TT;
    int s   = blockIdx.y;
    int sxl = tid / 24;          // 0..5 for active threads
    int q   = tid - sxl * 24;    // sensor-pair column 0..23

    unsigned mb[2]   = { smem_u32(&s_mb[0]), smem_u32(&s_mb[1]) };
    unsigned rdst[2] = { smem_u32(&s_rec[0][0]), smem_u32(&s_rec[1][0]) };
    unsigned gdst[2] = { smem_u32(&s_gy[0][0]),  smem_u32(&s_gy[1][0]) };
    if (tid == 0) { mbar_init(mb[0], 1); mbar_init(mb[1], 1); }
    __syncthreads();

    int blo = max(t0 - WCUT, 0) >> 2;
    int bhi = min(t0 + TT - 1 + WCUT, T_TICKS - 1) >> 2;
    int rb = g_soff[s * NB + blo], re = g_soff[s * NB + bhi + 1];
    int len = re - rb;
    int part = (len + NSPLIT - 1) / NSPLIT;
    int cb = rb + blockIdx.z * part;
    int ce = min(cb + part, re);
    int nch = (ce > cb) ? (ce - cb + CHUNK - 1) / CHUNK : 0;

    unsigned long long aa[4], ab[4];
#pragma unroll
    for (int j = 0; j < 4; j++) { aa[j] = 0ull; ab[j] = 0ull; }

    int ph0 = 0, ph1 = 0;

    // prefetch chunk 0
    if (nch > 0) {
        int cnt0 = min(CHUNK, ce - cb);
        if (tid == 0) mbar_expect_tx(mb[0], (unsigned)cnt0 * (RECB + GYB));
        __syncthreads();               // expect_tx ordered before completions
        if (tid == 0)
            bulk_g2s(rdst[0], (const char*)&g_ent[(size_t)cb * RECF4],
                     (unsigned)cnt0 * RECB, mb[0]);
        if (tid < cnt0) {
            int idx = g_eidx[cb + tid];
            bulk_g2s(gdst[0] + tid * GYB, g_cgy + (size_t)idx * 48, GYB, mb[0]);
        }
    }

    for (int ch = 0; ch < nch; ch++) {
        int c0  = cb + ch * CHUNK;
        int cnt = min(CHUNK, ce - c0);
        int buf = ch & 1;
        int nb_ = buf ^ 1;

        __syncthreads();                    // compute(ch-1) done: buf^1 + s_ev2 free
        int c1 = c0 + CHUNK;
        int cnt1 = (ch + 1 < nch) ? min(CHUNK, ce - c1) : 0;
        if (cnt1 > 0 && tid == 0)
            mbar_expect_tx(mb[nb_], (unsigned)cnt1 * (RECB + GYB));
        __syncthreads();                    // order expect before completions
        if (cnt1 > 0) {
            if (tid == 0)
                bulk_g2s(rdst[nb_], (const char*)&g_ent[(size_t)c1 * RECF4],
                         (unsigned)cnt1 * RECB, mb[nb_]);
            if (tid < cnt1) {
                int idx = g_eidx[c1 + tid];
                bulk_g2s(gdst[nb_] + tid * GYB, g_cgy + (size_t)idx * 48, GYB, mb[nb_]);
            }
        }
        // wait for chunk ch
        if (buf == 0) { mbar_wait(mb[0], ph0); ph0 ^= 1; }
        else          { mbar_wait(mb[1], ph1); ph1 ^= 1; }

        // ev via recurrence: exp(-0.1(d+1)^2) = exp(-0.1 d^2) * exp(-0.2 d - 0.1)
        if (tid < cnt) {
            float z  = ((const float*)&s_rec[buf][tid * RECF4])[6];
            float d  = (float)t0 - z;
            float e  = __expf(-0.1f * d * d);
            float rr = __expf(fmaf(-0.2f, d, -0.1f));
            const float rs = 0.81873075308f;   // exp(-0.2)
            float ev[8];
            ev[0] = e;
#pragma unroll
            for (int k = 1; k < 8; k++) {
                e *= rr; rr *= rs; ev[k] = e;
            }
            float4* dv = (float4*)&s_ev2[tid * 2];
            dv[0] = make_float4(ev[0], ev[1], ev[2], ev[3]);
            dv[1] = make_float4(ev[4], ev[5], ev[6], ev[7]);
        }
        __syncthreads();

        if (tid < ACT_D) {
            const float* gyb = s_gy[buf];
#pragma unroll 4
            for (int e = 0; e < cnt; e++) {
                float gxv = ((const float*)&s_rec[buf][e * RECF4])[sxl];
                float2 gy2 = *(const float2*)(gyb + e * 48 + 2 * q);
                unsigned long long va2 = pack2(gxv * gy2.x);
                unsigned long long vb2 = pack2(gxv * gy2.y);
                ulonglong2 w0 = s_ev2[e * 2 + 0];
                ulonglong2 w1 = s_ev2[e * 2 + 1];
                fma2(aa[0], va2, w0.x); fma2(ab[0], vb2, w0.x);
                fma2(aa[1], va2, w0.y); fma2(ab[1], vb2, w0.y);
                fma2(aa[2], va2, w1.x); fma2(ab[2], vb2, w1.x);
                fma2(aa[3], va2, w1.y); fma2(ab[3], vb2, w1.y);
            }
        }
    }

    if (tid < ACT_D) {
        float fa[8], fb[8];
#pragma unroll
        for (int j = 0; j < 4; j++) {
            unpack2(aa[j], fa[2 * j], fa[2 * j + 1]);
            unpack2(ab[j], fb[2 * j], fb[2 * j + 1]);
        }
        int sx = s * SXC + sxl;
        int sy = 2 * q;
        float* oa = out + ((size_t)(sx * NXY + sy)) * T_TICKS + t0;
        float* ob = out + ((size_t)(sx * NXY + sy + 1)) * T_TICKS + t0;
        red_add_v4(oa,     fa[0], fa[1], fa[2], fa[3]);
        red_add_v4(oa + 4, fa[4], fa[5], fa[6], fa[7]);
        red_add_v4(ob,     fb[0], fb[1], fb[2], fb[3]);
        red_add_v4(ob + 4, fb[4], fb[5], fb[6], fb[7]);
    }
}

// ------------------------------------------------------------------
extern "C" void kernel_launch(void* const* d_in, const int* in_sizes, int n_in,
                              void* d_out, int out_size)
{
    const float* si = (const float*)d_in[0];
    const float* zp = (const float*)d_in[1];
    const float* mk = (const float*)d_in[2];
    const float* W1 = (const float*)d_in[3];
    const float* b1 = (const float*)d_in[4];
    const float* W2 = (const float*)d_in[5];
    const float* b2 = (const float*)d_in[6];
    const float* W3 = (const float*)d_in[7];
    const float* b3 = (const float*)d_in[8];
    const float* el = (const float*)d_in[9];
    const float* sl = (const float*)d_in[10];
    float* out = (float*)d_out;                // (48,48,512)

    void* scnt_ptr = nullptr;
    cudaGetSymbolAddress(&scnt_ptr, g_scount);
    cudaMemsetAsync(scnt_ptr, 0, NSB * sizeof(int), 0);
    cudaMemsetAsync(d_out, 0, (size_t)out_size * sizeof(float), 0);

    k_pre    <<<(NEL + 63) / 64, 128>>>(si, zp, mk, W1, b1, W2, b2, W3, b3, el, sl);
    k_scan   <<<1, NSB>>>();
    k_scatter<<<(NEL + 31) / 32, 256>>>(el, sl);
    k_main   <<<dim3(NTILE, NSTRIP, NSPLIT), BLK_D>>>(out);
}